// round 15
// baseline (speedup 1.0000x reference)
#include <cuda_runtime.h>
#include <cstdint>

namespace {

constexpr int T_ = 128, H_ = 16, N_ = 64, C_ = 256, S_ = 129;
constexpr int NTHR  = 192;         // 6 warps/CTA
constexpr int NPW   = 5;           // producer warps per CTA
constexpr int NPROD = 10;          // producers per cluster
constexpr int TILE_BYTES = H_ * C_ * 4;   // 16KB per t-tile

constexpr float L2E  = 1.4426950408889634f;
constexpr float LN2  = 0.6931471805599453f;
constexpr float MINF = 1.17549435e-38f;    // 2^-126 == FLT_MIN == TINY

__device__ __forceinline__ float ex2f(float x) { float y; asm("ex2.approx.f32 %0, %1;" : "=f"(y) : "f"(x)); return y; }
__device__ __forceinline__ float lg2f(float x) { float y; asm("lg2.approx.f32 %0, %1;" : "=f"(y) : "f"(x)); return y; }

__device__ __forceinline__ uint32_t smem_u32(const void* p) {
    uint32_t a;
    asm("{ .reg .u64 t; cvta.to.shared.u64 t, %1; cvt.u32.u64 %0, t; }" : "=r"(a) : "l"(p));
    return a;
}
__device__ __forceinline__ uint32_t mapa_rank0(uint32_t local) {
    uint32_t r;
    asm("mapa.shared::cluster.u32 %0, %1, 0;" : "=r"(r) : "r"(local));
    return r;
}
__device__ __forceinline__ void st_cl_f32(uint32_t a, float v) {
    asm volatile("st.shared::cluster.f32 [%0], %1;" :: "r"(a), "f"(v));
}
__device__ __forceinline__ void mbar_init(uint32_t a, unsigned cnt) {
    asm volatile("mbarrier.init.shared.b64 [%0], %1;" :: "r"(a), "r"(cnt) : "memory");
}
__device__ __forceinline__ void mbar_expect_tx(uint32_t a, uint32_t bytes) {
    asm volatile("mbarrier.arrive.expect_tx.shared.b64 _, [%0], %1;"
                 :: "r"(a), "r"(bytes) : "memory");
}
__device__ __forceinline__ void mbar_arrive_cluster(uint32_t mapped) {
    asm volatile("mbarrier.arrive.release.cluster.shared::cluster.b64 _, [%0];"
                 :: "r"(mapped) : "memory");
}
__device__ __forceinline__ void mbar_wait(uint32_t a, uint32_t par) {
    asm volatile(
        "{\n\t.reg .pred P1;\n\t"
        "WL_%=:\n\t"
        "mbarrier.try_wait.parity.acquire.cta.shared::cta.b64 P1, [%0], %1, 0x989680;\n\t"
        "@P1 bra.uni WD_%=;\n\t"
        "bra.uni WL_%=;\n\t"
        "WD_%=:\n\t}"
        :: "r"(a), "r"(par) : "memory");
}
__device__ __forceinline__ void bulk_copy_1k(uint32_t dst, const void* src, uint32_t mbar) {
    asm volatile(
        "cp.async.bulk.shared::cta.global.mbarrier::complete_tx::bytes [%0], [%1], %2, [%3];"
        :: "r"(dst), "l"(src), "r"(1024), "r"(mbar) : "memory");
}
__device__ __forceinline__ void cluster_sync() {
    asm volatile("barrier.cluster.arrive.aligned;" ::: "memory");
    asm volatile("barrier.cluster.wait.aligned;" ::: "memory");
}
__device__ __forceinline__ uint32_t ctarank() {
    uint32_t r; asm("mov.u32 %0, %%cluster_ctarank;" : "=r"(r)); return r;
}

// 2-CTA cluster per n, 192 threads/CTA. Rank0: 5 producer warps + consumer
// (warp 5); rank1: 5 producers (warp 5 idle). Each producer warp double-
// buffers 16KB t-tiles fetched with cp.async.bulk (16 x 1KB rows per tile,
// expect_tx mbarrier), gathers the 65 deduped columns from SMEM, computes
// linear S[t][c] = sum_h 2^(cls+m), stores to rank0 S_sh via DSMEM, and
// release-arrives on group-of-4 mbarriers. Consumer: linear-domain recurrence.
__global__ __launch_bounds__(NTHR, 1) __cluster_dims__(2, 1, 1)
void fused_kernel(
    const float* __restrict__ mask,      // [T,H,N]
    const float* __restrict__ classify,  // [T,H,N,C]
    const int*   __restrict__ targets,   // [N,64]
    const int*   __restrict__ tlen,      // [N]
    float* __restrict__ out)             // [N]
{
    extern __shared__ float tiles[];     // NPW * 2 * 4096 floats (160KB)

    __shared__ float    S_sh[T_][68];    // linear per-column h-sums
    __shared__ uint64_t mbar_grp[T_ / 4];      // consumer row-group barriers
    __shared__ uint64_t mbar_tile[NPW][2];     // per-producer tile barriers
    __shared__ int      tgt_sh[64];
    __shared__ int      colv_sh[65];
    __shared__ int      cc_sh[T_];
    __shared__ float    res_sh[S_];

    const int n    = blockIdx.x >> 1;
    const int rank = (int)ctarank();
    const int tid  = threadIdx.x;
    const int w    = tid >> 5;
    const int lane = tid & 31;

    if (rank == 0 && tid < T_ / 4) mbar_init(smem_u32(&mbar_grp[tid]), 128);
    if (w < NPW && lane == 0) {
        mbar_init(smem_u32(&mbar_tile[w][0]), 1);
        mbar_init(smem_u32(&mbar_tile[w][1]), 1);
    }
    if (tid < 64) tgt_sh[tid] = targets[n * 64 + tid];
    __syncthreads();
    if (tid < 65) colv_sh[tid] = (tid == 0) ? 0 : tgt_sh[tid - 1];
    __syncthreads();
    cluster_sync();                 // all barriers live before any traffic

    const bool isProd = (w < NPW);

    if (isProd) {
        // ======================= producer warp =======================
        const int pid = rank * NPW + w;                   // 0..9
        const int nt  = (T_ - pid + NPROD - 1) / NPROD;   // 12 or 13
        float* tile0 = tiles + (size_t)(w * 2) * 4096;
        float* tile1 = tile0 + 4096;
        const uint32_t tb[2] = { smem_u32(tile0), smem_u32(tile1) };
        const uint32_t mb[2] = { smem_u32(&mbar_tile[w][0]), smem_u32(&mbar_tile[w][1]) };

        const int col1 = colv_sh[lane];
        const int col2 = colv_sh[32 + lane];
        const int col3 = colv_sh[64];
        const bool l31 = (lane == 31);

        // prologue: fill both slots
        if (lane == 0) {
#pragma unroll
            for (int s = 0; s < 2; ++s) {
                const int ts = pid + NPROD * s;
                if (s < nt) {
                    mbar_expect_tx(mb[s], TILE_BYTES);
                    for (int h = 0; h < H_; ++h)
                        bulk_copy_1k(tb[s] + h * 1024u,
                                     classify + (((size_t)ts * H_ + h) * N_ + n) * C_,
                                     mb[s]);
                }
            }
        }

        uint32_t par[2] = {0, 0};

        for (int i = 0; i < nt; ++i) {
            const int t    = pid + NPROD * i;
            const int slot = i & 1;
            // issue mask load before the tile wait (latency hidden)
            const float m = (lane < 16)
                ? __ldg(&mask[((size_t)t * H_ + lane) * N_ + n]) * L2E : 0.f;

            mbar_wait(mb[slot], par[slot]);
            par[slot] ^= 1;

            const float* tp = (slot == 0) ? tile0 : tile1;
            float s1 = 0.f, s2 = 0.f, s3 = 0.f;
#pragma unroll
            for (int h = 0; h < H_; ++h) {
                const float mh = __shfl_sync(0xffffffffu, m, h);
                const float* r = tp + h * C_;
                s1 += ex2f(__fmaf_rn(r[col1], L2E, mh));
                s2 += ex2f(__fmaf_rn(r[col2], L2E, mh));
                if (l31) s3 += ex2f(__fmaf_rn(r[col3], L2E, mh));
            }

            // write linear sums into rank0's S_sh, arrive on group barrier
            const uint32_t r0 = mapa_rank0(smem_u32(&S_sh[t][0]));
            st_cl_f32(r0 + 4u * lane,        s1);
            st_cl_f32(r0 + 4u * (32 + lane), s2);
            if (l31) st_cl_f32(r0 + 4u * 64, s3);
            mbar_arrive_cluster(mapa_rank0(smem_u32(&mbar_grp[t >> 2])));

            __syncwarp();   // all lanes done reading the tile before refill

            const int t2 = pid + NPROD * (i + 2);
            if (t2 < T_ && lane == 0) {
                mbar_expect_tx(mb[slot], TILE_BYTES);
                for (int h = 0; h < H_; ++h)
                    bulk_copy_1k(tb[slot] + h * 1024u,
                                 classify + (((size_t)t2 * H_ + h) * N_ + n) * C_,
                                 mb[slot]);
            }
        }
        return;
    }

    if (rank != 0) return;          // rank1 warp 5 idles

    // =================== consumer warp (rank0, w == 5) ===================
    const int NS = (lane == 31) ? 5 : 4;
    const int sB = 4 * lane;

    // cc prefix scan (reachability frontier)
    {
        int c[4], pfx = 0;
#pragma unroll
        for (int i = 0; i < 4; ++i) {
            int u = 4 * lane + i, v = 0;
            if (u >= 2) {
                int sk = 0;
                if ((u & 1) && u >= 3) sk = (tgt_sh[(u - 1) >> 1] != tgt_sh[(u - 3) >> 1]);
                v = sk + 1;
            }
            pfx += v; c[i] = pfx;
        }
        int tot = pfx;
#pragma unroll
        for (int d = 1; d < 32; d <<= 1) {
            int up = __shfl_up_sync(0xffffffffu, tot, d);
            if (lane >= d) tot += up;
        }
        int excl = tot - pfx;
#pragma unroll
        for (int i = 0; i < 4; ++i) {
            int u = 4 * lane + i;
            if (u >= 1) cc_sh[u] = 2 + excl + c[i];
        }
    }
    __syncwarp();

    bool skipb[5];
#pragma unroll
    for (int i = 0; i < 5; ++i) {
        int s = sB + i;
        skipb[i] = (i < NS) && (s & 1) && (s >= 3) &&
                   (tgt_sh[(s - 1) >> 1] != tgt_sh[(s - 3) >> 1]);
    }

    const int cO1 = 2 * lane + 1;   // entry of state 4l+1
    const int cO2 = 2 * lane + 2;   // entry of state 4l+3

    // linear-domain state: P[i] = 2^np[i]
    float P[5];
#pragma unroll
    for (int i = 0; i < 5; ++i) P[i] = (sB + i < 2) ? 1.f : 0.f;

    float fE = 0.f, fO1 = 0.f, fO2 = 0.f;   // S values of row 127 (final)

    for (int g = 0; g < T_ / 4; ++g) {
        mbar_wait(smem_u32(&mbar_grp[g]), 0);
        float sE[4], sO1[4], sO2[4];
#pragma unroll
        for (int k = 0; k < 4; ++k) {
            const int r = 4 * g + k;
            sE[k]  = S_sh[r][0];
            sO1[k] = S_sh[r][cO1];
            sO2[k] = S_sh[r][cO2];
        }
#pragma unroll
        for (int k = 0; k < 4; ++k) {
            const int r = 4 * g + k;
            if (r == 127) { fE = sE[k]; fO1 = sO1[k]; fO2 = sO2[k]; break; }
            const int cc_t = cc_sh[r + 1];

            // e = max(P*S, TINY); unreachable -> TINY
            float e[5];
            e[0] = fmaxf(P[0] * sE[k],  MINF);
            e[1] = fmaxf(P[1] * sO1[k], MINF);
            e[2] = fmaxf(P[2] * sE[k],  MINF);
            e[3] = fmaxf(P[3] * sO2[k], MINF);
            e[4] = fmaxf(P[4] * sE[k],  MINF);
#pragma unroll
            for (int i = 0; i < 5; ++i)
                if (sB + i > cc_t) e[i] = MINF;

            const float em1 = __shfl_up_sync(0xffffffffu, e[3], 1);
            const float em2 = __shfl_up_sync(0xffffffffu, e[2], 1);

            float Pn[5];
            Pn[0] = (lane == 0) ? e[0] : e[0] + em1 + (skipb[0] ? em2 : 0.f);
            Pn[1] = e[1] + e[0] + (skipb[1] ? em1 : 0.f);
#pragma unroll
            for (int i = 2; i < 5; ++i)
                Pn[i] = e[i] + e[i - 1] + (skipb[i] ? e[i - 2] : 0.f);
#pragma unroll
            for (int i = 0; i < 5; ++i) P[i] = Pn[i];
        }
    }

    // final: res2[s] = lg2(P[s]) + lg2(S127[entry])
    const float lE  = lg2f(fE), lO1 = lg2f(fO1), lO2 = lg2f(fO2);
    res_sh[sB + 0] = lg2f(P[0]) + lE;
    res_sh[sB + 1] = lg2f(P[1]) + lO1;
    res_sh[sB + 2] = lg2f(P[2]) + lE;
    res_sh[sB + 3] = lg2f(P[3]) + lO2;
    if (lane == 31) res_sh[128] = lg2f(P[4]) + lE;
    __syncwarp();

    if (lane == 0) {
        const int   L = 2 * tlen[n] + 1;
        const float x = res_sh[L - 1], y = res_sh[L - 2];
        const float mx = fmaxf(x, y);
        const float l2 = mx + lg2f(ex2f(x - mx) + ex2f(y - mx));
        out[n] = -((LN2 * l2) / (float)tlen[n]);
    }
}

} // anonymous namespace

extern "C" void kernel_launch(void* const* d_in, const int* /*in_sizes*/, int /*n_in*/,
                              void* d_out, int /*out_size*/) {
    const float* mask     = (const float*)d_in[0];
    const float* classify = (const float*)d_in[1];
    const int*   targets  = (const int*)d_in[2];
    // d_in[3] = input_lengths (always T, unused)
    const int*   tlen     = (const int*)d_in[4];

    const int dyn = NPW * 2 * TILE_BYTES;   // 160KB
    cudaFuncSetAttribute(fused_kernel, cudaFuncAttributeMaxDynamicSharedMemorySize, dyn);
    fused_kernel<<<2 * N_, NTHR, dyn>>>(mask, classify, targets, tlen, (float*)d_out);
}

// round 16
// speedup vs baseline: 1.3292x; 1.3292x over previous
#include <cuda_runtime.h>
#include <cstdint>

namespace {

constexpr int T_ = 128, H_ = 16, N_ = 64, C_ = 256, S_ = 129;
constexpr int NC_ = N_ * C_;
constexpr int NPROD = 31;          // producers per n: 15 (rank0) + 16 (rank1)

constexpr float L2E  = 1.4426950408889634f;
constexpr float LN2  = 0.6931471805599453f;
constexpr float MINF = 1.17549435e-38f;        // 2^-126 == FLT_MIN == TINY

__device__ __forceinline__ float ex2f(float x) { float y; asm("ex2.approx.f32 %0, %1;" : "=f"(y) : "f"(x)); return y; }
__device__ __forceinline__ float lg2f(float x) { float y; asm("lg2.approx.f32 %0, %1;" : "=f"(y) : "f"(x)); return y; }

__device__ __forceinline__ uint32_t smem_u32(const void* p) {
    uint32_t a;
    asm("{ .reg .u64 t; cvta.to.shared.u64 t, %1; cvt.u32.u64 %0, t; }" : "=r"(a) : "l"(p));
    return a;
}
__device__ __forceinline__ uint32_t mapa_rank0(uint32_t local) {
    uint32_t r;
    asm("mapa.shared::cluster.u32 %0, %1, 0;" : "=r"(r) : "r"(local));
    return r;
}
__device__ __forceinline__ void st_cl_f32(uint32_t a, float v) {
    asm volatile("st.shared::cluster.f32 [%0], %1;" :: "r"(a), "f"(v));
}
__device__ __forceinline__ void mbar_init(uint32_t a, unsigned cnt) {
    asm volatile("mbarrier.init.shared.b64 [%0], %1;" :: "r"(a), "r"(cnt) : "memory");
}
__device__ __forceinline__ void mbar_arrive_cluster(uint32_t mapped) {
    asm volatile("mbarrier.arrive.release.cluster.shared::cluster.b64 _, [%0];"
                 :: "r"(mapped) : "memory");
}
__device__ __forceinline__ void mbar_wait0(uint32_t a) {
    uint32_t done;
    asm volatile(
        "{\n\t.reg .pred p;\n\t"
        "mbarrier.try_wait.parity.acquire.cta.shared::cta.b64 p, [%1], 0;\n\t"
        "selp.b32 %0, 1, 0, p;\n\t}"
        : "=r"(done) : "r"(a) : "memory");
    if (!done) {
        asm volatile(
            "{\n\t.reg .pred P1;\n\t"
            "WL_%=:\n\t"
            "mbarrier.try_wait.parity.acquire.cta.shared::cta.b64 P1, [%0], 0, 0x989680;\n\t"
            "@P1 bra.uni WD_%=;\n\t"
            "bra.uni WL_%=;\n\t"
            "WD_%=:\n\t}"
            :: "r"(a) : "memory");
    }
}
__device__ __forceinline__ void cluster_sync() {
    asm volatile("barrier.cluster.arrive.aligned;" ::: "memory");
    asm volatile("barrier.cluster.wait.aligned;" ::: "memory");
}
__device__ __forceinline__ uint32_t ctarank() {
    uint32_t r; asm("mov.u32 %0, %%cluster_ctarank;" : "=r"(r)); return r;
}

// Issue the gather loads for row t into register set (Ax, Bx, c3x, mx).
#define ISSUE(Ax, Bx, c3x, mx, t) do {                                         \
    const float* base_ = classify + (size_t)(t) * H_ * NC_;                    \
    _Pragma("unroll")                                                          \
    for (int h_ = 0; h_ < H_; ++h_) {                                          \
        const size_t ho_ = (size_t)h_ * NC_;                                   \
        Ax[h_] = __ldg(base_ + ho_ + b1);                                      \
        Bx[h_] = __ldg(base_ + ho_ + b2);                                      \
    }                                                                          \
    if (lane < 16) {                                                           \
        c3x = __ldg(base_ + (size_t)lane * NC_ + b3);                          \
        mx  = __ldg(&mask[((size_t)(t) * H_ + lane) * N_ + n]) * L2E;          \
    }                                                                          \
} while (0)

// Reduce over h, store linear sums for row t into rank0's S_sh, arrive.
#define CSTORE(Ax, Bx, c3x, mx, t) do {                                        \
    float s1_ = 0.f, s2_ = 0.f;                                                \
    _Pragma("unroll")                                                          \
    for (int h_ = 0; h_ < H_; ++h_) {                                          \
        const float mh_ = __shfl_sync(0xffffffffu, mx, h_);                    \
        s1_ += ex2f(__fmaf_rn(Ax[h_], L2E, mh_));                              \
        s2_ += ex2f(__fmaf_rn(Bx[h_], L2E, mh_));                              \
    }                                                                          \
    float s3_ = (lane < 16) ? ex2f(__fmaf_rn(c3x, L2E, mx)) : 0.f;             \
    s3_ += __shfl_xor_sync(0xffffffffu, s3_, 8);                               \
    s3_ += __shfl_xor_sync(0xffffffffu, s3_, 4);                               \
    s3_ += __shfl_xor_sync(0xffffffffu, s3_, 2);                               \
    s3_ += __shfl_xor_sync(0xffffffffu, s3_, 1);                               \
    const uint32_t r0_ = mapa_rank0(smem_u32(&S_sh[(t)][0]));                  \
    st_cl_f32(r0_ + 4u * oi1, s1_);                                            \
    st_cl_f32(r0_ + 4u * oi2, s2_);                                            \
    if (lane == 0) st_cl_f32(r0_ + 4u * oi3, s3_);                             \
    mbar_arrive_cluster(mapa_rank0(smem_u32(&mbar[(t) >> 2])));                \
} while (0)

// 2-CTA cluster per n, 512 threads/CTA. Rank0: 15 producer warps + consumer
// warp 15; rank1: 16 producers. Producers gather the 65 deduped columns with
// SORTED column->lane assignment (minimal sector wavefronts) and a 2-row
// register software pipeline: row t+31's loads are issued BEFORE row t's
// reduction, keeping a full row of loads in flight at all times. Column 64 is
// loaded cooperatively by lanes 0-15 (one head each, xor-reduced). Linear
// S[t][c] = sum_h 2^(cls+m) written to rank0 smem at original column index;
// release-arrive on group-of-4 mbarriers. Consumer: linear-domain recurrence.
__global__ __launch_bounds__(512, 1) __cluster_dims__(2, 1, 1)
void fused_kernel(
    const float* __restrict__ mask,      // [T,H,N]
    const float* __restrict__ classify,  // [T,H,N,C]
    const int*   __restrict__ targets,   // [N,64]
    const int*   __restrict__ tlen,      // [N]
    float* __restrict__ out)             // [N]
{
    __shared__ float    S_sh[T_][68];    // linear per-column h-sums
    __shared__ uint64_t mbar[T_ / 4];    // one barrier per 4-row group
    __shared__ int      tgt_sh[64];
    __shared__ int      cc_sh[T_];
    __shared__ float    res_sh[S_];
    __shared__ int      colv_sh[65];     // entry -> column value
    __shared__ int      scol_sh[65];     // rank  -> column value (sorted)
    __shared__ int      sidx_sh[65];     // rank  -> original entry index

    const int n    = blockIdx.x >> 1;
    const int rank = (int)ctarank();
    const int tid  = threadIdx.x;
    const int w    = tid >> 5;
    const int lane = tid & 31;

    if (rank == 0 && tid < T_ / 4) mbar_init(smem_u32(&mbar[tid]), 128);
    if (tid < 64) tgt_sh[tid] = targets[n * 64 + tid];
    __syncthreads();

    if (tid < 65) colv_sh[tid] = (tid == 0) ? 0 : tgt_sh[tid - 1];
    __syncthreads();
    // warp-parallel rank sort (ties broken by index -> rank is a permutation)
    if (tid < 65) {
        const int v = colv_sh[tid];
        int r = 0;
        for (int j = 0; j < 65; ++j) {
            const int u = colv_sh[j];
            r += (u < v) || (u == v && j < tid);
        }
        scol_sh[r] = v;
        sidx_sh[r] = tid;
    }
    __syncthreads();
    cluster_sync();                 // barriers + tables live before producing

    const bool isProd = (rank == 1) || (w < 15);

    if (isProd) {
        // ======================= producer warp =======================
        const int pid = (rank == 0) ? w : (15 + w);   // 0..30
        const int sc1 = scol_sh[lane],      oi1 = sidx_sh[lane];
        const int sc2 = scol_sh[32 + lane], oi2 = sidx_sh[32 + lane];
        const int sc3 = scol_sh[64],        oi3 = sidx_sh[64];
        const size_t b1 = (size_t)n * C_ + sc1;
        const size_t b2 = (size_t)n * C_ + sc2;
        const size_t b3 = (size_t)n * C_ + sc3;

        float A0[H_], B0[H_], A1[H_], B1[H_];
        float c30 = 0.f, c31 = 0.f, m0 = 0.f, m1 = 0.f;

        int t = pid;
        ISSUE(A0, B0, c30, m0, t);
        for (;;) {
            int tn = t + NPROD;
            if (tn < T_) ISSUE(A1, B1, c31, m1, tn);
            CSTORE(A0, B0, c30, m0, t);
            t = tn;
            if (t >= T_) break;

            tn = t + NPROD;
            if (tn < T_) ISSUE(A0, B0, c30, m0, tn);
            CSTORE(A1, B1, c31, m1, t);
            t = tn;
            if (t >= T_) break;
        }
        return;
    }

    // =================== consumer warp (rank0, w == 15) ===================
    const int NS = (lane == 31) ? 5 : 4;
    const int sB = 4 * lane;

    // cc prefix scan (reachability frontier)
    {
        int c[4], pfx = 0;
#pragma unroll
        for (int i = 0; i < 4; ++i) {
            int u = 4 * lane + i, v = 0;
            if (u >= 2) {
                int sk = 0;
                if ((u & 1) && u >= 3) sk = (tgt_sh[(u - 1) >> 1] != tgt_sh[(u - 3) >> 1]);
                v = sk + 1;
            }
            pfx += v; c[i] = pfx;
        }
        int tot = pfx;
#pragma unroll
        for (int d = 1; d < 32; d <<= 1) {
            int up = __shfl_up_sync(0xffffffffu, tot, d);
            if (lane >= d) tot += up;
        }
        int excl = tot - pfx;
#pragma unroll
        for (int i = 0; i < 4; ++i) {
            int u = 4 * lane + i;
            if (u >= 1) cc_sh[u] = 2 + excl + c[i];
        }
    }
    __syncwarp();

    bool skipb[5];
#pragma unroll
    for (int i = 0; i < 5; ++i) {
        int s = sB + i;
        skipb[i] = (i < NS) && (s & 1) && (s >= 3) &&
                   (tgt_sh[(s - 1) >> 1] != tgt_sh[(s - 3) >> 1]);
    }

    const int cO1 = 2 * lane + 1;   // entry of state 4l+1
    const int cO2 = 2 * lane + 2;   // entry of state 4l+3

    // linear-domain state: P[i] = 2^np[i]
    float P[5];
#pragma unroll
    for (int i = 0; i < 5; ++i) P[i] = (sB + i < 2) ? 1.f : 0.f;

    float fE = 0.f, fO1 = 0.f, fO2 = 0.f;   // S values of row 127 (final)

    for (int g = 0; g < T_ / 4; ++g) {
        mbar_wait0(smem_u32(&mbar[g]));
        float sE[4], sO1[4], sO2[4];
#pragma unroll
        for (int k = 0; k < 4; ++k) {
            const int r = 4 * g + k;
            sE[k]  = S_sh[r][0];
            sO1[k] = S_sh[r][cO1];
            sO2[k] = S_sh[r][cO2];
        }
#pragma unroll
        for (int k = 0; k < 4; ++k) {
            const int r = 4 * g + k;
            if (r == 127) { fE = sE[k]; fO1 = sO1[k]; fO2 = sO2[k]; break; }
            const int cc_t = cc_sh[r + 1];

            // e = max(P*S, TINY); unreachable -> TINY
            float e[5];
            e[0] = fmaxf(P[0] * sE[k],  MINF);
            e[1] = fmaxf(P[1] * sO1[k], MINF);
            e[2] = fmaxf(P[2] * sE[k],  MINF);
            e[3] = fmaxf(P[3] * sO2[k], MINF);
            e[4] = fmaxf(P[4] * sE[k],  MINF);
#pragma unroll
            for (int i = 0; i < 5; ++i)
                if (sB + i > cc_t) e[i] = MINF;

            const float em1 = __shfl_up_sync(0xffffffffu, e[3], 1);
            const float em2 = __shfl_up_sync(0xffffffffu, e[2], 1);

            float Pn[5];
            Pn[0] = (lane == 0) ? e[0] : e[0] + em1 + (skipb[0] ? em2 : 0.f);
            Pn[1] = e[1] + e[0] + (skipb[1] ? em1 : 0.f);
#pragma unroll
            for (int i = 2; i < 5; ++i)
                Pn[i] = e[i] + e[i - 1] + (skipb[i] ? e[i - 2] : 0.f);
#pragma unroll
            for (int i = 0; i < 5; ++i) P[i] = Pn[i];
        }
    }

    // final: res2[s] = lg2(P[s]) + lg2(S127[entry])
    const float lE  = lg2f(fE), lO1 = lg2f(fO1), lO2 = lg2f(fO2);
    res_sh[sB + 0] = lg2f(P[0]) + lE;
    res_sh[sB + 1] = lg2f(P[1]) + lO1;
    res_sh[sB + 2] = lg2f(P[2]) + lE;
    res_sh[sB + 3] = lg2f(P[3]) + lO2;
    if (lane == 31) res_sh[128] = lg2f(P[4]) + lE;
    __syncwarp();

    if (lane == 0) {
        const int   L = 2 * tlen[n] + 1;
        const float x = res_sh[L - 1], y = res_sh[L - 2];
        const float mx = fmaxf(x, y);
        const float l2 = mx + lg2f(ex2f(x - mx) + ex2f(y - mx));
        out[n] = -((LN2 * l2) / (float)tlen[n]);
    }
}

} // anonymous namespace

extern "C" void kernel_launch(void* const* d_in, const int* /*in_sizes*/, int /*n_in*/,
                              void* d_out, int /*out_size*/) {
    const float* mask     = (const float*)d_in[0];
    const float* classify = (const float*)d_in[1];
    const int*   targets  = (const int*)d_in[2];
    // d_in[3] = input_lengths (always T, unused)
    const int*   tlen     = (const int*)d_in[4];

    fused_kernel<<<2 * N_, 512>>>(mask, classify, targets, tlen, (float*)d_out);
}